// round 5
// baseline (speedup 1.0000x reference)
#include <cuda_runtime.h>
#include <cuda_bf16.h>
#include <cstdint>

// Problem constants
#define BB 4
#define SS 2048
#define DD 1024
#define HH 16
#define HD 64
#define NT (BB * SS)        // 8192 tokens
#define D3 (3 * DD)         // 3072

// ---------------------------------------------------------------------------
// Scratch (device globals — no runtime allocation)
// ---------------------------------------------------------------------------
static __device__ __nv_bfloat16  g_qkvh[(size_t)NT * D3];   // qkv hi/lo (bf16)
static __device__ __nv_bfloat16  g_qkvl[(size_t)NT * D3];
static __device__ __nv_bfloat16  g_xh[(size_t)NT * DD];     // hidden hi/lo
static __device__ __nv_bfloat16  g_xl[(size_t)NT * DD];
static __device__ __nv_bfloat16  g_ah[(size_t)NT * DD];     // attn out hi/lo
static __device__ __nv_bfloat16  g_al[(size_t)NT * DD];
static __device__ __nv_bfloat16  g_wqh[(size_t)D3 * DD];    // c_attn_w^T hi/lo [N][K]
static __device__ __nv_bfloat16  g_wql[(size_t)D3 * DD];
static __device__ __nv_bfloat16  g_wph[(size_t)DD * DD];    // c_proj_w^T hi/lo
static __device__ __nv_bfloat16  g_wpl[(size_t)DD * DD];

// ---------------------------------------------------------------------------
__device__ __forceinline__ uint32_t smem_u32(const void* p) {
    uint32_t a;
    asm("{ .reg .u64 t; cvta.to.shared.u64 t, %1; cvt.u32.u64 %0, t; }" : "=r"(a) : "l"(p));
    return a;
}

#define CP_ASYNC16(saddr, gptr) \
    asm volatile("cp.async.cg.shared.global [%0], [%1], 16;" :: "r"(saddr), "l"(gptr) : "memory")
#define CP_COMMIT()  asm volatile("cp.async.commit_group;" ::: "memory")
#define CP_WAIT0()   asm volatile("cp.async.wait_group 0;" ::: "memory")
#define CP_WAIT1()   asm volatile("cp.async.wait_group 1;" ::: "memory")
#define CP_WAIT2()   asm volatile("cp.async.wait_group 2;" ::: "memory")

#define LDMATRIX_X4(r0, r1, r2, r3, addr) \
    asm volatile("ldmatrix.sync.aligned.m8n8.x4.shared.b16 {%0,%1,%2,%3}, [%4];" \
        : "=r"(r0), "=r"(r1), "=r"(r2), "=r"(r3) : "r"(addr))

#define LDMATRIX_X4_T(r0, r1, r2, r3, addr) \
    asm volatile("ldmatrix.sync.aligned.m8n8.x4.trans.shared.b16 {%0,%1,%2,%3}, [%4];" \
        : "=r"(r0), "=r"(r1), "=r"(r2), "=r"(r3) : "r"(addr))

#define MMA_BF16(c, a, b) \
    asm volatile("mma.sync.aligned.m16n8k16.row.col.f32.bf16.bf16.f32 " \
        "{%0,%1,%2,%3}, {%4,%5,%6,%7}, {%8,%9}, {%0,%1,%2,%3};" \
        : "+f"((c)[0]), "+f"((c)[1]), "+f"((c)[2]), "+f"((c)[3]) \
        : "r"((a)[0]), "r"((a)[1]), "r"((a)[2]), "r"((a)[3]), "r"((b)[0]), "r"((b)[1]))

__device__ __forceinline__ uint32_t pack_bf16(float a, float b) {
    __nv_bfloat162 t = __floats2bfloat162_rn(a, b);
    return *reinterpret_cast<uint32_t*>(&t);
}

// ---------------------------------------------------------------------------
// Conversion kernels
// ---------------------------------------------------------------------------
__global__ void act_split(const float4* __restrict__ x,
                          uint2* __restrict__ hi, uint2* __restrict__ lo, int n4) {
    int i = blockIdx.x * blockDim.x + threadIdx.x;
    if (i >= n4) return;
    float4 v = x[i];
    float vv[4] = {v.x, v.y, v.z, v.w};
    union { uint2 u; __nv_bfloat16 b[4]; } H, L;
#pragma unroll
    for (int j = 0; j < 4; j++) {
        __nv_bfloat16 h = __float2bfloat16(vv[j]);
        H.b[j] = h;
        L.b[j] = __float2bfloat16(vv[j] - __bfloat162float(h));
    }
    hi[i] = H.u; lo[i] = L.u;
}

__global__ void wt_split_t(const float* __restrict__ W,
                           __nv_bfloat16* __restrict__ hi, __nv_bfloat16* __restrict__ lo,
                           int K, int N) {
    __shared__ float t[32][33];
    const int kb = blockIdx.y * 32, nb = blockIdx.x * 32;
    const int tx = threadIdx.x, ty = threadIdx.y;
#pragma unroll
    for (int i = 0; i < 32; i += 8)
        t[ty + i][tx] = W[(size_t)(kb + ty + i) * N + nb + tx];
    __syncthreads();
#pragma unroll
    for (int i = 0; i < 32; i += 8) {
        float v = t[tx][ty + i];
        __nv_bfloat16 h = __float2bfloat16(v);
        size_t o = (size_t)(nb + ty + i) * K + kb + tx;
        hi[o] = h;
        lo[o] = __float2bfloat16(v - __bfloat162float(h));
    }
}

// ---------------------------------------------------------------------------
// HMMA GEMM: C = (Ahi+Alo)[M,K] @ (Bhi+Blo)[N,K]^T + bias
// 128x128 CTA tile, 512 threads (4x4 warps, 32x32 each), BK=32,
// 3-stage cp.async pipeline, 3-term bf16 split, fp32 accum.
// ---------------------------------------------------------------------------
#define BKC 32
#define ROWB 80
#define TILEB (128 * ROWB)            // 10240
#define STAGEB (4 * TILEB)            // 40960
#define GSMEM (3 * STAGEB)            // 122880

extern __shared__ char g_dsmem[];

__global__ void __launch_bounds__(512, 1) gemm_mma(
    const __nv_bfloat16* __restrict__ Ahi, const __nv_bfloat16* __restrict__ Alo,
    const __nv_bfloat16* __restrict__ Bhi, const __nv_bfloat16* __restrict__ Blo,
    const float* __restrict__ bias, float* __restrict__ Cf,
    __nv_bfloat16* __restrict__ Ch, __nv_bfloat16* __restrict__ Cl,
    int M, int N, int K)
{
    const int tid  = threadIdx.x;
    const int wid  = tid >> 5;
    const int lane = tid & 31;
    const int wm   = wid >> 2;        // 0..3
    const int wn   = wid & 3;         // 0..3
    const int bm = blockIdx.y, bn = blockIdx.x;

    const __nv_bfloat16* srcs[4] = {
        Ahi + (size_t)(bm * 128) * K,
        Alo + (size_t)(bm * 128) * K,
        Bhi + (size_t)(bn * 128) * K,
        Blo + (size_t)(bn * 128) * K
    };

    const uint32_t sb = smem_u32(g_dsmem);

    float acc[2][4][4];
#pragma unroll
    for (int i = 0; i < 2; i++)
#pragma unroll
        for (int j = 0; j < 4; j++)
#pragma unroll
            for (int v = 0; v < 4; v++) acc[i][j][v] = 0.0f;

    const int NS = K / BKC;           // 32

    // one cp.async per (thread, tile): 512 threads cover 128 rows x 4 chunks
    const int ld_r = tid >> 2;
    const int ld_c = tid & 3;
    auto load_stage = [&](int s, int buf) {
        const int k0 = s * BKC;
        const uint32_t base = sb + buf * STAGEB + ld_r * ROWB + ld_c * 16;
        const size_t go = (size_t)ld_r * K + k0 + ld_c * 8;
#pragma unroll
        for (int tile = 0; tile < 4; tile++)
            CP_ASYNC16(base + tile * TILEB, srcs[tile] + go);
        CP_COMMIT();
    };

    load_stage(0, 0);
    load_stage(1, 1);
    load_stage(2, 2);

    const int a_row  = (lane & 15);
    const int a_koff = (lane >> 4) * 16;
    const int b_blk  = lane >> 3;
    const int b_row8 = lane & 7;
    const int b_noff = ((b_blk >> 1) << 3) + b_row8;
    const int b_koff = (b_blk & 1) * 16;

    int buf = 0;
    for (int s = 0; s < NS; s++) {
        if (s <= NS - 3)      CP_WAIT2();
        else if (s == NS - 2) CP_WAIT1();
        else                  CP_WAIT0();
        __syncthreads();

        const uint32_t st = sb + buf * STAGEB;
#pragma unroll
        for (int ks = 0; ks < 2; ks++) {
            const int kb = ks * 32;

            uint32_t ah[2][4], al[2][4], bh[4][2], bl[4][2];
#pragma unroll
            for (int mt = 0; mt < 2; mt++) {
                const uint32_t ar = st + (wm * 32 + mt * 16 + a_row) * ROWB + kb + a_koff;
                LDMATRIX_X4(ah[mt][0], ah[mt][1], ah[mt][2], ah[mt][3], ar);
                LDMATRIX_X4(al[mt][0], al[mt][1], al[mt][2], al[mt][3], ar + TILEB);
            }
#pragma unroll
            for (int p = 0; p < 2; p++) {
                const uint32_t br = st + 2 * TILEB +
                    (wn * 32 + p * 16 + b_noff) * ROWB + kb + b_koff;
                LDMATRIX_X4(bh[2 * p][0], bh[2 * p][1], bh[2 * p + 1][0], bh[2 * p + 1][1], br);
                LDMATRIX_X4(bl[2 * p][0], bl[2 * p][1], bl[2 * p + 1][0], bl[2 * p + 1][1], br + TILEB);
            }

#pragma unroll
            for (int mt = 0; mt < 2; mt++)
#pragma unroll
                for (int nt = 0; nt < 4; nt++) {
                    MMA_BF16(acc[mt][nt], ah[mt], bh[nt]);
                    MMA_BF16(acc[mt][nt], al[mt], bh[nt]);
                    MMA_BF16(acc[mt][nt], ah[mt], bl[nt]);
                }
        }
        __syncthreads();
        if (s + 3 < NS) load_stage(s + 3, buf);
        buf = (buf == 2) ? 0 : buf + 1;
    }

    const int r0 = bm * 128 + wm * 32 + (lane >> 2);
    const int c0 = bn * 128 + wn * 32 + (lane & 3) * 2;
    if (Cf) {
#pragma unroll
        for (int mt = 0; mt < 2; mt++)
#pragma unroll
            for (int nt = 0; nt < 4; nt++) {
                const int row = r0 + mt * 16;
                const int col = c0 + nt * 8;
                float2 o0, o1;
                o0.x = acc[mt][nt][0] + bias[col];
                o0.y = acc[mt][nt][1] + bias[col + 1];
                o1.x = acc[mt][nt][2] + bias[col];
                o1.y = acc[mt][nt][3] + bias[col + 1];
                *(float2*)(Cf + (size_t)row * N + col) = o0;
                *(float2*)(Cf + (size_t)(row + 8) * N + col) = o1;
            }
    } else {
#pragma unroll
        for (int mt = 0; mt < 2; mt++)
#pragma unroll
            for (int nt = 0; nt < 4; nt++) {
                const int row = r0 + mt * 16;
                const int col = c0 + nt * 8;
                const float b0 = bias[col], b1 = bias[col + 1];
#pragma unroll
                for (int hf = 0; hf < 2; hf++) {
                    const float v0 = acc[mt][nt][2 * hf]     + b0;
                    const float v1 = acc[mt][nt][2 * hf + 1] + b1;
                    const float h0 = __bfloat162float(__float2bfloat16(v0));
                    const float h1 = __bfloat162float(__float2bfloat16(v1));
                    const size_t off = (size_t)(row + 8 * hf) * N + col;
                    *(uint32_t*)(Ch + off) = pack_bf16(h0, h1);
                    *(uint32_t*)(Cl + off) = pack_bf16(v0 - h0, v1 - h1);
                }
            }
    }
}

// ---------------------------------------------------------------------------
// Tensor-core causal flash attention (unchanged from R4).
// ---------------------------------------------------------------------------
#define AROWB 144
#define ATILE (64 * AROWB)
#define ASTAGE (4 * ATILE)
#define ASMEM (2 * ASTAGE)

__global__ void __launch_bounds__(256) attn_mma(
    const __nv_bfloat16* __restrict__ QKVh, const __nv_bfloat16* __restrict__ QKVl,
    __nv_bfloat16* __restrict__ Oh, __nv_bfloat16* __restrict__ Ol)
{
    const int tid  = threadIdx.x;
    const int wid  = tid >> 5;
    const int lane = tid & 31;
    const int qtile = (gridDim.x - 1) - blockIdx.x;
    const int bh = blockIdx.y;
    const int b  = bh >> 4;
    const int h  = bh & 15;
    const int bS = b * SS;
    const int qbase = qtile * 128 + wid * 16;

    const uint32_t sb = smem_u32(g_dsmem);

#pragma unroll
    for (int i = 0; i < 4; i++) {
        const int idx = i * 256 + tid;
        const int r = idx >> 3, c = idx & 7;
        const size_t g = (size_t)(bS + qtile * 128 + r) * D3 + h * HD + c * 8;
        CP_ASYNC16(sb + r * AROWB + c * 16, QKVh + g);
        CP_ASYNC16(sb + 128 * AROWB + r * AROWB + c * 16, QKVl + g);
    }
    CP_COMMIT();
    CP_WAIT0();
    __syncthreads();

    uint32_t qh[4][4], ql[4][4];
    const int a_row  = lane & 15;
    const int a_koff = (lane >> 4) * 16;
    {
        const uint32_t qr = sb + (wid * 16 + a_row) * AROWB + a_koff;
#pragma unroll
        for (int ks = 0; ks < 4; ks++) {
            LDMATRIX_X4(qh[ks][0], qh[ks][1], qh[ks][2], qh[ks][3], qr + ks * 32);
            LDMATRIX_X4(ql[ks][0], ql[ks][1], ql[ks][2], ql[ks][3],
                        qr + 128 * AROWB + ks * 32);
        }
    }
    __syncthreads();

    auto load_kv = [&](int kt, int buf) {
        const int k0 = kt * 64;
        const uint32_t base = sb + buf * ASTAGE;
#pragma unroll
        for (int i = 0; i < 8; i++) {
            const int idx  = i * 256 + tid;
            const int tile = idx >> 9;
            const int r    = (idx >> 3) & 63;
            const int c    = idx & 7;
            const size_t g = (size_t)(bS + k0 + r) * D3 +
                             ((tile < 2) ? DD : 2 * DD) + h * HD + c * 8;
            const __nv_bfloat16* src = (tile & 1) ? QKVl : QKVh;
            CP_ASYNC16(base + tile * ATILE + r * AROWB + c * 16, src + g);
        }
        CP_COMMIT();
    };

    float o[8][4];
#pragma unroll
    for (int n = 0; n < 8; n++)
#pragma unroll
        for (int j = 0; j < 4; j++) o[n][j] = 0.0f;
    float mrow[2] = {-1e30f, -1e30f};
    float lrow[2] = {0.0f, 0.0f};

    const int b_blk  = lane >> 3;
    const int b_row8 = lane & 7;
    const int b_noff = ((b_blk >> 1) << 3) + b_row8;
    const int b_koff = (b_blk & 1) * 16;
    const int v_row  = lane & 15;
    const int v_coff = ((lane >> 4) & 1) * 16;

    const int ntl = 2 * qtile + 2;
    load_kv(0, 0);

    for (int kt = 0; kt < ntl; kt++) {
        const int buf = kt & 1;
        const int k0 = kt * 64;
        if (kt + 1 < ntl) { load_kv(kt + 1, buf ^ 1); CP_WAIT1(); }
        else              { CP_WAIT0(); }
        __syncthreads();

        if (k0 <= qbase + 15) {
            const uint32_t kbse = sb + buf * ASTAGE;
            const uint32_t vbse = kbse + 2 * ATILE;

            float s[8][4];
#pragma unroll
            for (int n = 0; n < 8; n++)
#pragma unroll
                for (int j = 0; j < 4; j++) s[n][j] = 0.0f;

#pragma unroll
            for (int p = 0; p < 4; p++) {
#pragma unroll
                for (int ks = 0; ks < 4; ks++) {
                    uint32_t kh[4], kl[4];
                    const uint32_t ar = kbse + (p * 16 + b_noff) * AROWB + ks * 32 + b_koff;
                    LDMATRIX_X4(kh[0], kh[1], kh[2], kh[3], ar);
                    LDMATRIX_X4(kl[0], kl[1], kl[2], kl[3], ar + ATILE);
                    uint32_t bh0[2] = {kh[0], kh[1]}, bh1[2] = {kh[2], kh[3]};
                    uint32_t bl0[2] = {kl[0], kl[1]}, bl1[2] = {kl[2], kl[3]};
                    MMA_BF16(s[2 * p],     qh[ks], bh0);
                    MMA_BF16(s[2 * p],     ql[ks], bh0);
                    MMA_BF16(s[2 * p],     qh[ks], bl0);
                    MMA_BF16(s[2 * p + 1], qh[ks], bh1);
                    MMA_BF16(s[2 * p + 1], ql[ks], bh1);
                    MMA_BF16(s[2 * p + 1], qh[ks], bl1);
                }
            }

            const bool need_mask = (k0 + 63 > qbase);
            const int row0 = qbase + (lane >> 2);
            const int colb = k0 + (lane & 3) * 2;
#pragma unroll
            for (int hf = 0; hf < 2; hf++) {
                const int row = row0 + 8 * hf;
                float mx = mrow[hf];
#pragma unroll
                for (int n = 0; n < 8; n++) {
                    float v0 = s[n][2 * hf]     * 0.125f;
                    float v1 = s[n][2 * hf + 1] * 0.125f;
                    if (need_mask) {
                        const int col = colb + 8 * n;
                        if (col > row)     v0 = -1e30f;
                        if (col + 1 > row) v1 = -1e30f;
                    }
                    s[n][2 * hf] = v0; s[n][2 * hf + 1] = v1;
                    mx = fmaxf(mx, fmaxf(v0, v1));
                }
                mx = fmaxf(mx, __shfl_xor_sync(0xffffffffu, mx, 1));
                mx = fmaxf(mx, __shfl_xor_sync(0xffffffffu, mx, 2));
                const float alpha = __expf(mrow[hf] - mx);
                lrow[hf] *= alpha;
#pragma unroll
                for (int n = 0; n < 8; n++) {
                    o[n][2 * hf]     *= alpha;
                    o[n][2 * hf + 1] *= alpha;
                }
                float ls = 0.0f;
#pragma unroll
                for (int n = 0; n < 8; n++) {
                    const float p0 = __expf(s[n][2 * hf]     - mx);
                    const float p1 = __expf(s[n][2 * hf + 1] - mx);
                    s[n][2 * hf] = p0; s[n][2 * hf + 1] = p1;
                    ls += p0 + p1;
                }
                lrow[hf] += ls;
                mrow[hf] = mx;
            }

#pragma unroll
            for (int ks = 0; ks < 4; ks++) {
                uint32_t ph[4], pl[4];
#pragma unroll
                for (int q2 = 0; q2 < 2; q2++) {
                    const float* pv = s[2 * ks + q2];
#pragma unroll
                    for (int e = 0; e < 2; e++) {
                        const float v0 = pv[2 * e], v1 = pv[2 * e + 1];
                        const float h0 = __bfloat162float(__float2bfloat16(v0));
                        const float h1 = __bfloat162float(__float2bfloat16(v1));
                        ph[q2 * 2 + e] = pack_bf16(h0, h1);
                        pl[q2 * 2 + e] = pack_bf16(v0 - h0, v1 - h1);
                    }
                }
#pragma unroll
                for (int np = 0; np < 4; np++) {
                    uint32_t vh[4], vl[4];
                    const uint32_t va = vbse + (ks * 16 + v_row) * AROWB + np * 32 + v_coff;
                    LDMATRIX_X4_T(vh[0], vh[1], vh[2], vh[3], va);
                    LDMATRIX_X4_T(vl[0], vl[1], vl[2], vl[3], va + ATILE);
                    uint32_t vh0[2] = {vh[0], vh[1]}, vh1[2] = {vh[2], vh[3]};
                    uint32_t vl0[2] = {vl[0], vl[1]}, vl1[2] = {vl[2], vl[3]};
                    MMA_BF16(o[2 * np],     ph, vh0);
                    MMA_BF16(o[2 * np],     pl, vh0);
                    MMA_BF16(o[2 * np],     ph, vl0);
                    MMA_BF16(o[2 * np + 1], ph, vh1);
                    MMA_BF16(o[2 * np + 1], pl, vh1);
                    MMA_BF16(o[2 * np + 1], ph, vl1);
                }
            }
        }
        __syncthreads();
    }

    float inv[2];
#pragma unroll
    for (int hf = 0; hf < 2; hf++) {
        float l = lrow[hf];
        l += __shfl_xor_sync(0xffffffffu, l, 1);
        l += __shfl_xor_sync(0xffffffffu, l, 2);
        inv[hf] = 1.0f / l;
    }
    const int row0 = qbase + (lane >> 2);
    const int colb = h * HD + (lane & 3) * 2;
#pragma unroll
    for (int hf = 0; hf < 2; hf++) {
        const size_t rof = (size_t)(bS + row0 + 8 * hf) * DD;
#pragma unroll
        for (int n = 0; n < 8; n++) {
            const float v0 = o[n][2 * hf]     * inv[hf];
            const float v1 = o[n][2 * hf + 1] * inv[hf];
            const float h0 = __bfloat162float(__float2bfloat16(v0));
            const float h1 = __bfloat162float(__float2bfloat16(v1));
            const size_t off = rof + colb + n * 8;
            *(uint32_t*)(Oh + off) = pack_bf16(h0, h1);
            *(uint32_t*)(Ol + off) = pack_bf16(v0 - h0, v1 - h1);
        }
    }
}

// ---------------------------------------------------------------------------
extern "C" void kernel_launch(void* const* d_in, const int* in_sizes, int n_in,
                              void* d_out, int out_size)
{
    const float* hidden   = (const float*)d_in[0];
    const float* c_attn_w = (const float*)d_in[1];
    const float* c_attn_b = (const float*)d_in[2];
    const float* c_proj_w = (const float*)d_in[3];
    const float* c_proj_b = (const float*)d_in[4];
    float* out = (float*)d_out;

    __nv_bfloat16 *qkvh, *qkvl, *xh, *xl, *ah, *al, *wqh, *wql, *wph, *wpl;
    cudaGetSymbolAddress((void**)&qkvh, g_qkvh);
    cudaGetSymbolAddress((void**)&qkvl, g_qkvl);
    cudaGetSymbolAddress((void**)&xh,  g_xh);
    cudaGetSymbolAddress((void**)&xl,  g_xl);
    cudaGetSymbolAddress((void**)&ah,  g_ah);
    cudaGetSymbolAddress((void**)&al,  g_al);
    cudaGetSymbolAddress((void**)&wqh, g_wqh);
    cudaGetSymbolAddress((void**)&wql, g_wql);
    cudaGetSymbolAddress((void**)&wph, g_wph);
    cudaGetSymbolAddress((void**)&wpl, g_wpl);

    cudaFuncSetAttribute(gemm_mma, cudaFuncAttributeMaxDynamicSharedMemorySize, GSMEM);
    cudaFuncSetAttribute(attn_mma, cudaFuncAttributeMaxDynamicSharedMemorySize, ASMEM);

    wt_split_t<<<dim3(D3 / 32, DD / 32), dim3(32, 8)>>>(c_attn_w, wqh, wql, DD, D3);
    wt_split_t<<<dim3(DD / 32, DD / 32), dim3(32, 8)>>>(c_proj_w, wph, wpl, DD, DD);

    {
        const int n4 = NT * DD / 4;
        act_split<<<(n4 + 255) / 256, 256>>>((const float4*)hidden, (uint2*)xh, (uint2*)xl, n4);
    }

    // 1) QKV projection -> bf16 hi/lo directly
    gemm_mma<<<dim3(D3 / 128, NT / 128), 512, GSMEM>>>(
        xh, xl, wqh, wql, c_attn_b, nullptr, qkvh, qkvl, NT, D3, DD);

    // 2) tensor-core causal flash attention
    attn_mma<<<dim3(SS / 128, BB * HH), 256, ASMEM>>>(qkvh, qkvl, ah, al);

    // 3) output projection -> fp32
    gemm_mma<<<dim3(DD / 128, NT / 128), 512, GSMEM>>>(
        ah, al, wph, wpl, c_proj_b, out, nullptr, nullptr, NT, DD, DD);
}